// round 6
// baseline (speedup 1.0000x reference)
#include <cuda_runtime.h>
#include <cuda_bf16.h>
#include <math.h>
#include <stdint.h>

// Problem constants (fixed by setup_inputs)
#define BSZ    2
#define LSEQ   1024
#define HDIM   2048
#define DDIM   4096
#define NSTATE 16
#define RRANK  128
#define KCONV  4
#define BL     (BSZ * LSEQ)          // 2048 rows
#define P2D    (2 * DDIM)            // 8192
#define SP_W   (RRANK + 2 * NSTATE)  // 160
#define XP_SPLIT 8                   // split-K factor for x_proj
#define XP_KLEN  (DDIM / XP_SPLIT)   // 512

// ---------------------------------------------------------------------------
// Scratch: static device globals (no cudaMalloc allowed)
// ---------------------------------------------------------------------------
__device__ float g_proj[(size_t)BL * P2D];     // in_proj output [BL, 8192] (u | gate)
__device__ float g_sp  [(size_t)BL * SP_W];    // x_proj output [BL, 160]
__device__ float g_dt  [(size_t)BL * DDIM];    // softplus(dt_proj) [BL, D]
__device__ float g_xpp [(size_t)XP_SPLIT * BL * SP_W];  // split-K partials

// bf16 hi/lo split buffers
__device__ __nv_bfloat16 g_hs_h[(size_t)BL * HDIM],  g_hs_l[(size_t)BL * HDIM];
__device__ __nv_bfloat16 g_win_h[(size_t)P2D * HDIM], g_win_l[(size_t)P2D * HDIM];
__device__ __nv_bfloat16 g_u_h[(size_t)BL * DDIM],   g_u_l[(size_t)BL * DDIM];
__device__ __nv_bfloat16 g_wx_h[(size_t)SP_W * DDIM], g_wx_l[(size_t)SP_W * DDIM];
__device__ __nv_bfloat16 g_sp_h[(size_t)BL * SP_W],  g_sp_l[(size_t)BL * SP_W];
__device__ __nv_bfloat16 g_wdt_h[(size_t)DDIM * RRANK], g_wdt_l[(size_t)DDIM * RRANK];
__device__ __nv_bfloat16 g_y_h[(size_t)BL * DDIM],   g_y_l[(size_t)BL * DDIM];
__device__ __nv_bfloat16 g_wo_h[(size_t)HDIM * DDIM], g_wo_l[(size_t)HDIM * DDIM];

__device__ __forceinline__ float softplusf(float x) {
    return (x > 20.f) ? x : log1pf(__expf(x));
}
__device__ __forceinline__ float siluf(float x) {
    return x / (1.f + __expf(-x));
}

// ---------------------------------------------------------------------------
// PTX helpers (sm_80+ portable: cp.async / ldmatrix / mma.sync)
// ---------------------------------------------------------------------------
__device__ __forceinline__ uint32_t smem_u32(const void* p) {
    uint32_t a;
    asm("{ .reg .u64 t; cvta.to.shared.u64 t, %1; cvt.u32.u64 %0, t; }" : "=r"(a) : "l"(p));
    return a;
}
__device__ __forceinline__ void cpa16(uint32_t dst, const void* src, int sz) {
    asm volatile("cp.async.cg.shared.global [%0], [%1], 16, %2;"
                 :: "r"(dst), "l"(src), "r"(sz) : "memory");
}
__device__ __forceinline__ void cpa16f(uint32_t dst, const void* src) {
    asm volatile("cp.async.cg.shared.global [%0], [%1], 16;"
                 :: "r"(dst), "l"(src) : "memory");
}
__device__ __forceinline__ void cpa_commit() {
    asm volatile("cp.async.commit_group;" ::: "memory");
}
template <int N>
__device__ __forceinline__ void cpa_wait() {
    asm volatile("cp.async.wait_group %0;" :: "n"(N) : "memory");
}
__device__ __forceinline__ void ldsm_x4(uint32_t* r, uint32_t addr) {
    asm volatile("ldmatrix.sync.aligned.m8n8.x4.shared.b16 {%0,%1,%2,%3}, [%4];"
                 : "=r"(r[0]), "=r"(r[1]), "=r"(r[2]), "=r"(r[3]) : "r"(addr));
}
__device__ __forceinline__ void mma_bf16(float* c, const uint32_t* a, const uint32_t* b) {
    asm volatile(
        "mma.sync.aligned.m16n8k16.row.col.f32.bf16.bf16.f32 "
        "{%0,%1,%2,%3}, {%4,%5,%6,%7}, {%8,%9}, {%0,%1,%2,%3};"
        : "+f"(c[0]), "+f"(c[1]), "+f"(c[2]), "+f"(c[3])
        : "r"(a[0]), "r"(a[1]), "r"(a[2]), "r"(a[3]), "r"(b[0]), "r"(b[1]));
}

// ---------------------------------------------------------------------------
// Merged fp32 -> bf16 hi/lo split for all 5 weight/input tensors (1 launch)
// ---------------------------------------------------------------------------
#define CVT_N0 (BL * HDIM / 4)                       // hs
#define CVT_N1 (CVT_N0 + P2D * HDIM / 4)             // + w_in
#define CVT_N2 (CVT_N1 + SP_W * DDIM / 4)            // + w_x
#define CVT_N3 (CVT_N2 + DDIM * RRANK / 4)           // + w_dt
#define CVT_N4 (CVT_N3 + HDIM * DDIM / 4)            // + w_o

__device__ __forceinline__ void cvt_one(const float* __restrict__ x,
                                        __nv_bfloat16* __restrict__ h,
                                        __nv_bfloat16* __restrict__ l, int i)
{
    float4 v = ((const float4*)x)[i];
    __nv_bfloat162 h0 = __floats2bfloat162_rn(v.x, v.y);
    __nv_bfloat162 h1 = __floats2bfloat162_rn(v.z, v.w);
    __nv_bfloat162 l0 = __floats2bfloat162_rn(v.x - __low2float(h0), v.y - __high2float(h0));
    __nv_bfloat162 l1 = __floats2bfloat162_rn(v.z - __low2float(h1), v.w - __high2float(h1));
    ((__nv_bfloat162*)h)[2 * i]     = h0;
    ((__nv_bfloat162*)h)[2 * i + 1] = h1;
    ((__nv_bfloat162*)l)[2 * i]     = l0;
    ((__nv_bfloat162*)l)[2 * i + 1] = l1;
}

__global__ void cvt_all(const float* s0, __nv_bfloat16* h0, __nv_bfloat16* l0,
                        const float* s1, __nv_bfloat16* h1, __nv_bfloat16* l1,
                        const float* s2, __nv_bfloat16* h2, __nv_bfloat16* l2,
                        const float* s3, __nv_bfloat16* h3, __nv_bfloat16* l3,
                        const float* s4, __nv_bfloat16* h4, __nv_bfloat16* l4)
{
    int i = blockIdx.x * blockDim.x + threadIdx.x;
    if (i < CVT_N0)      cvt_one(s0, h0, l0, i);
    else if (i < CVT_N1) cvt_one(s1, h1, l1, i - CVT_N0);
    else if (i < CVT_N2) cvt_one(s2, h2, l2, i - CVT_N1);
    else if (i < CVT_N3) cvt_one(s3, h3, l3, i - CVT_N2);
    else if (i < CVT_N4) cvt_one(s4, h4, l4, i - CVT_N3);
}

// ===========================================================================
// BIG tensor-core split-bf16 GEMM: CTA tile 256x128, 8 warps, warp tile 64x64.
//   C[m,n] = Ah*Bh + Ah*Bl + Al*Bh (fp32 acc), BK=32, 3-stage cp.async.
// Rationale: halves per-warp A/B fragment re-reads vs 64x32 warp tiles, so the
// smem crossbar (the measured bottleneck) serves 2x the FLOPs per byte.
// Requires M%256==0, N%128==0, K%32==0 (true for in/dt/out projections).
// EPI==1: C = softplus(C + bias[n])
// ===========================================================================
#define BTILE_A  16384               // 256 rows x 64B
#define BTILE_B  8192                // 128 rows x 64B
#define BSTAGE   (2 * BTILE_A + 2 * BTILE_B)   // Ah | Al | Bh | Bl = 48KB
#define BNSTAGE  3
#define BDYN_SMEM (BNSTAGE * BSTAGE)           // 144KB

__device__ __forceinline__ void load_tileA256(
    const __nv_bfloat16* __restrict__ src, int ld, int row0, int k0,
    uint32_t dstbase, int tid)
{
#pragma unroll
    for (int i = 0; i < 4; i++) {
        const int u   = tid + i * 256;        // 0..1023
        const int row = u >> 2;               // 0..255
        const int s   = u & 3;
        const uint32_t off = (uint32_t)(row * 64 + ((s * 16) ^ ((row & 6) << 3)));
        cpa16f(dstbase + off, src + (size_t)(row0 + row) * ld + k0 + s * 8);
    }
}
__device__ __forceinline__ void load_tileB128(
    const __nv_bfloat16* __restrict__ src, int ld, int row0, int k0,
    uint32_t dstbase, int tid)
{
#pragma unroll
    for (int i = 0; i < 2; i++) {
        const int u   = tid + i * 256;        // 0..511
        const int row = u >> 2;               // 0..127
        const int s   = u & 3;
        const uint32_t off = (uint32_t)(row * 64 + ((s * 16) ^ ((row & 6) << 3)));
        cpa16f(dstbase + off, src + (size_t)(row0 + row) * ld + k0 + s * 8);
    }
}

template <int EPI>
__global__ void __launch_bounds__(256, 1)
tgemm_big(const __nv_bfloat16* __restrict__ Ah, const __nv_bfloat16* __restrict__ Al, int lda,
          const __nv_bfloat16* __restrict__ Bh, const __nv_bfloat16* __restrict__ Bl, int ldb,
          float* __restrict__ C, int ldc, int klen, const float* __restrict__ bias)
{
    extern __shared__ __align__(1024) char smem[];
    const uint32_t sbase = smem_u32(smem);

    const int tid  = threadIdx.x;
    const int wid  = tid >> 5;
    const int lane = tid & 31;
    const int m0   = blockIdx.y * 256;
    const int n0   = blockIdx.x * 128;
    const int wm   = wid >> 1;             // 0..3 -> 64-row slab
    const int wn   = wid & 1;              // 0..1 -> 64-col slab

    const uint32_t khiA = (uint32_t)((lane >> 4) * 16);
    const uint32_t khiB = (uint32_t)(((lane >> 3) & 1) * 16);
    uint32_t pA[4], xA[4], pB[4], xB[4];
#pragma unroll
    for (int i = 0; i < 4; i++) {
        const int r = wm * 64 + i * 16 + (lane & 15);
        pA[i] = (uint32_t)(r * 64);
        xA[i] = (uint32_t)((r & 6) << 3);
    }
#pragma unroll
    for (int j2 = 0; j2 < 4; j2++) {
        const int r = wn * 64 + j2 * 16 + ((lane >> 4) << 3) + (lane & 7);
        pB[j2] = (uint32_t)(r * 64);
        xB[j2] = (uint32_t)((r & 6) << 3);
    }

    float acc[4][8][4];
#pragma unroll
    for (int i = 0; i < 4; i++)
#pragma unroll
        for (int j = 0; j < 8; j++)
#pragma unroll
            for (int r = 0; r < 4; r++) acc[i][j][r] = 0.f;

    const int nch = klen >> 5;

    // prologue
#pragma unroll
    for (int s = 0; s < BNSTAGE - 1; s++) {
        if (s < nch) {
            uint32_t st = sbase + s * BSTAGE;
            const int k0 = s << 5;
            load_tileA256(Ah, lda, m0, k0, st,                tid);
            load_tileA256(Al, lda, m0, k0, st + BTILE_A,      tid);
            load_tileB128(Bh, ldb, n0, k0, st + 2 * BTILE_A,           tid);
            load_tileB128(Bl, ldb, n0, k0, st + 2 * BTILE_A + BTILE_B, tid);
        }
        cpa_commit();
    }

    for (int c = 0; c < nch; c++) {
        cpa_wait<BNSTAGE - 2>();
        __syncthreads();

        const int cp = c + BNSTAGE - 1;
        if (cp < nch) {
            uint32_t st = sbase + (cp % BNSTAGE) * BSTAGE;
            const int k0 = cp << 5;
            load_tileA256(Ah, lda, m0, k0, st,                tid);
            load_tileA256(Al, lda, m0, k0, st + BTILE_A,      tid);
            load_tileB128(Bh, ldb, n0, k0, st + 2 * BTILE_A,           tid);
            load_tileB128(Bl, ldb, n0, k0, st + 2 * BTILE_A + BTILE_B, tid);
        }
        cpa_commit();

        const uint32_t aH = sbase + (c % BNSTAGE) * BSTAGE;
        const uint32_t aL = aH + BTILE_A;
        const uint32_t bH = aH + 2 * BTILE_A;
        const uint32_t bL = bH + BTILE_B;

#pragma unroll
        for (int ks = 0; ks < 2; ks++) {
            const uint32_t kA = (uint32_t)(ks * 32) + khiA;
            const uint32_t kB = (uint32_t)(ks * 32) + khiB;
            uint32_t ah[4][4], al[4][4];
#pragma unroll
            for (int i = 0; i < 4; i++) {
                ldsm_x4(ah[i], aH + pA[i] + (kA ^ xA[i]));
                ldsm_x4(al[i], aL + pA[i] + (kA ^ xA[i]));
            }
#pragma unroll
            for (int j2 = 0; j2 < 4; j2++) {
                uint32_t bh[4], bl[4];
                ldsm_x4(bh, bH + pB[j2] + (kB ^ xB[j2]));
                ldsm_x4(bl, bL + pB[j2] + (kB ^ xB[j2]));
                // term-major: acc reuse distance = 8 independent MMAs
#pragma unroll
                for (int i = 0; i < 4; i++) {
                    mma_bf16(acc[i][2 * j2 + 0], ah[i], &bh[0]);
                    mma_bf16(acc[i][2 * j2 + 1], ah[i], &bh[2]);
                }
#pragma unroll
                for (int i = 0; i < 4; i++) {
                    mma_bf16(acc[i][2 * j2 + 0], ah[i], &bl[0]);
                    mma_bf16(acc[i][2 * j2 + 1], ah[i], &bl[2]);
                }
#pragma unroll
                for (int i = 0; i < 4; i++) {
                    mma_bf16(acc[i][2 * j2 + 0], al[i], &bh[0]);
                    mma_bf16(acc[i][2 * j2 + 1], al[i], &bh[2]);
                }
            }
        }
    }

    // epilogue
    const int qr = lane >> 2;
    const int qc = (lane & 3) * 2;
#pragma unroll
    for (int i = 0; i < 4; i++) {
        const int r0 = m0 + wm * 64 + i * 16 + qr;
#pragma unroll
        for (int j = 0; j < 8; j++) {
            const int nn = n0 + wn * 64 + j * 8 + qc;
            float2 v0 = make_float2(acc[i][j][0], acc[i][j][1]);
            float2 v1 = make_float2(acc[i][j][2], acc[i][j][3]);
            if (EPI == 1) {
                const float b0 = bias[nn], b1 = bias[nn + 1];
                v0.x = softplusf(v0.x + b0); v0.y = softplusf(v0.y + b1);
                v1.x = softplusf(v1.x + b0); v1.y = softplusf(v1.y + b1);
            }
            *(float2*)(C + (size_t)r0 * ldc + nn)       = v0;
            *(float2*)(C + (size_t)(r0 + 8) * ldc + nn) = v1;
        }
    }
}

// ---------------------------------------------------------------------------
// Small split-bf16 GEMM (128x128 tile) — used for x_proj split-K (N=160)
// ---------------------------------------------------------------------------
#define TILE_BYTES  8192
#define STAGE_BYTES (4 * TILE_BYTES)
#define NSTAGE      3
#define DYN_SMEM    (NSTAGE * STAGE_BYTES)

template <bool GUARD>
__device__ __forceinline__ void load_tile_async(
    const __nv_bfloat16* __restrict__ src, int ld, int row0, int k0,
    uint32_t dstbase, int tid, int nrows)
{
#pragma unroll
    for (int i = 0; i < 2; i++) {
        const int u   = tid + i * 256;
        const int row = u >> 2;
        const int s   = u & 3;
        const uint32_t off = (uint32_t)(row * 64 + ((s * 16) ^ ((row & 6) << 3)));
        if (GUARD) {
            const int ok = (row0 + row) < nrows;
            const void* p = src + (size_t)(row0 + (ok ? row : 0)) * ld + k0 + s * 8;
            cpa16(dstbase + off, p, ok ? 16 : 0);
        } else {
            cpa16f(dstbase + off, src + (size_t)(row0 + row) * ld + k0 + s * 8);
        }
    }
}

template <int EPI, bool GUARD>
__global__ void __launch_bounds__(256, 2)
tgemm(const __nv_bfloat16* __restrict__ Ah, const __nv_bfloat16* __restrict__ Al, int lda,
      const __nv_bfloat16* __restrict__ Bh, const __nv_bfloat16* __restrict__ Bl, int ldb,
      float* __restrict__ C, int ldc, int Nc, int klen,
      const float* __restrict__ bias, size_t partStride)
{
    extern __shared__ __align__(1024) char smem[];
    const uint32_t sbase = smem_u32(smem);

    const int tid  = threadIdx.x;
    const int wid  = tid >> 5;
    const int lane = tid & 31;
    const int m0   = blockIdx.y * 128;
    const int n0   = blockIdx.x * 128;
    const int kb   = blockIdx.z * klen;
    C += (size_t)blockIdx.z * partStride;
    const int wm   = wid >> 2;
    const int wn   = wid & 3;

    const uint32_t khiA = (uint32_t)((lane >> 4) * 16);
    const uint32_t khiB = (uint32_t)(((lane >> 3) & 1) * 16);
    uint32_t pA[4], xA[4], pB[2], xB[2];
#pragma unroll
    for (int i = 0; i < 4; i++) {
        const int r = wm * 64 + i * 16 + (lane & 15);
        pA[i] = (uint32_t)(r * 64);
        xA[i] = (uint32_t)((r & 6) << 3);
    }
#pragma unroll
    for (int j2 = 0; j2 < 2; j2++) {
        const int r = wn * 32 + j2 * 16 + ((lane >> 4) << 3) + (lane & 7);
        pB[j2] = (uint32_t)(r * 64);
        xB[j2] = (uint32_t)((r & 6) << 3);
    }

    float acc[4][4][4];
#pragma unroll
    for (int i = 0; i < 4; i++)
#pragma unroll
        for (int j = 0; j < 4; j++)
#pragma unroll
            for (int r = 0; r < 4; r++) acc[i][j][r] = 0.f;

    const int nch = klen >> 5;

#pragma unroll
    for (int s = 0; s < NSTAGE - 1; s++) {
        if (s < nch) {
            uint32_t st = sbase + s * STAGE_BYTES;
            const int k0 = kb + (s << 5);
            load_tile_async<false>(Ah, lda, m0, k0, st,                  tid, 0);
            load_tile_async<false>(Al, lda, m0, k0, st + TILE_BYTES,     tid, 0);
            load_tile_async<GUARD>(Bh, ldb, n0, k0, st + 2 * TILE_BYTES, tid, Nc);
            load_tile_async<GUARD>(Bl, ldb, n0, k0, st + 3 * TILE_BYTES, tid, Nc);
        }
        cpa_commit();
    }

    for (int c = 0; c < nch; c++) {
        cpa_wait<NSTAGE - 2>();
        __syncthreads();

        const int cp = c + NSTAGE - 1;
        if (cp < nch) {
            uint32_t st = sbase + (cp % NSTAGE) * STAGE_BYTES;
            const int k0 = kb + (cp << 5);
            load_tile_async<false>(Ah, lda, m0, k0, st,                  tid, 0);
            load_tile_async<false>(Al, lda, m0, k0, st + TILE_BYTES,     tid, 0);
            load_tile_async<GUARD>(Bh, ldb, n0, k0, st + 2 * TILE_BYTES, tid, Nc);
            load_tile_async<GUARD>(Bl, ldb, n0, k0, st + 3 * TILE_BYTES, tid, Nc);
        }
        cpa_commit();

        const uint32_t aH = sbase + (c % NSTAGE) * STAGE_BYTES;
        const uint32_t aL = aH + TILE_BYTES;
        const uint32_t bH = aH + 2 * TILE_BYTES;
        const uint32_t bL = aH + 3 * TILE_BYTES;

#pragma unroll
        for (int ks = 0; ks < 2; ks++) {
            const uint32_t kA = (uint32_t)(ks * 32) + khiA;
            const uint32_t kB = (uint32_t)(ks * 32) + khiB;
            uint32_t ah[4][4], al[4][4];
#pragma unroll
            for (int i = 0; i < 4; i++) {
                ldsm_x4(ah[i], aH + pA[i] + (kA ^ xA[i]));
                ldsm_x4(al[i], aL + pA[i] + (kA ^ xA[i]));
            }
            uint32_t bh[2][4], bl[2][4];
#pragma unroll
            for (int j2 = 0; j2 < 2; j2++) {
                ldsm_x4(bh[j2], bH + pB[j2] + (kB ^ xB[j2]));
                ldsm_x4(bl[j2], bL + pB[j2] + (kB ^ xB[j2]));
            }
            // term-major: acc reuse distance = 16 independent MMAs
#pragma unroll
            for (int j = 0; j < 4; j++)
#pragma unroll
                for (int i = 0; i < 4; i++)
                    mma_bf16(acc[i][j], ah[i], &bh[j >> 1][(j & 1) * 2]);
#pragma unroll
            for (int j = 0; j < 4; j++)
#pragma unroll
                for (int i = 0; i < 4; i++)
                    mma_bf16(acc[i][j], ah[i], &bl[j >> 1][(j & 1) * 2]);
#pragma unroll
            for (int j = 0; j < 4; j++)
#pragma unroll
                for (int i = 0; i < 4; i++)
                    mma_bf16(acc[i][j], al[i], &bh[j >> 1][(j & 1) * 2]);
        }
    }

    const int qr = lane >> 2;
    const int qc = (lane & 3) * 2;
#pragma unroll
    for (int i = 0; i < 4; i++) {
        const int r0 = m0 + wm * 64 + i * 16 + qr;
#pragma unroll
        for (int j = 0; j < 4; j++) {
            const int nn = n0 + wn * 32 + j * 8 + qc;
            if (!GUARD || nn < Nc) {
                float2 v0 = make_float2(acc[i][j][0], acc[i][j][1]);
                float2 v1 = make_float2(acc[i][j][2], acc[i][j][3]);
                if (EPI == 1) {
                    const float b0 = bias[nn], b1 = bias[nn + 1];
                    v0.x = softplusf(v0.x + b0); v0.y = softplusf(v0.y + b1);
                    v1.x = softplusf(v1.x + b0); v1.y = softplusf(v1.y + b1);
                }
                *(float2*)(C + (size_t)r0 * ldc + nn)       = v0;
                *(float2*)(C + (size_t)(r0 + 8) * ldc + nn) = v1;
            }
        }
    }
}

// ---------------------------------------------------------------------------
// split-K reduce for x_proj: sp = sum(partials); also emit bf16 hi/lo
// ---------------------------------------------------------------------------
__global__ void xp_reduce(const float* __restrict__ part,
                          float* __restrict__ sp,
                          __nv_bfloat16* __restrict__ sph,
                          __nv_bfloat16* __restrict__ spl)
{
    const int n4 = BL * SP_W / 4;
    int i = blockIdx.x * blockDim.x + threadIdx.x;
    if (i >= n4) return;
    float4 a = ((const float4*)part)[i];
#pragma unroll
    for (int p = 1; p < XP_SPLIT; p++) {
        float4 b = ((const float4*)part)[i + (size_t)p * n4];
        a.x += b.x; a.y += b.y; a.z += b.z; a.w += b.w;
    }
    ((float4*)sp)[i] = a;
    __nv_bfloat162 h0 = __floats2bfloat162_rn(a.x, a.y);
    __nv_bfloat162 h1 = __floats2bfloat162_rn(a.z, a.w);
    __nv_bfloat162 l0 = __floats2bfloat162_rn(a.x - __low2float(h0), a.y - __high2float(h0));
    __nv_bfloat162 l1 = __floats2bfloat162_rn(a.z - __low2float(h1), a.w - __high2float(h1));
    ((__nv_bfloat162*)sph)[2 * i]     = h0;
    ((__nv_bfloat162*)sph)[2 * i + 1] = h1;
    ((__nv_bfloat162*)spl)[2 * i]     = l0;
    ((__nv_bfloat162*)spl)[2 * i + 1] = l1;
}

// ---------------------------------------------------------------------------
// Depthwise causal conv1d (K=4) + bias + silu -> bf16 hi/lo
// ---------------------------------------------------------------------------
__global__ void conv_silu_kernel(const float* __restrict__ proj,
                                 const float* __restrict__ cw,
                                 const float* __restrict__ cb,
                                 __nv_bfloat16* __restrict__ uh,
                                 __nv_bfloat16* __restrict__ ul)
{
    const int idx = blockIdx.x * blockDim.x + threadIdx.x;
    if (idx >= BL * DDIM) return;
    const int d  = idx & (DDIM - 1);
    const int bl = idx >> 12;
    const int l  = bl & (LSEQ - 1);

    const float4 w = *(const float4*)(cw + d * 4);
    const float* base = proj + (size_t)bl * P2D + d;
    float acc = cb[d];
    if (l >= 3) acc = fmaf(w.x, base[-3 * P2D], acc);
    if (l >= 2) acc = fmaf(w.y, base[-2 * P2D], acc);
    if (l >= 1) acc = fmaf(w.z, base[-1 * P2D], acc);
    acc = fmaf(w.w, base[0], acc);
    const float v = siluf(acc);
    const __nv_bfloat16 h = __float2bfloat16(v);
    uh[idx] = h;
    ul[idx] = __float2bfloat16(v - __bfloat162float(h));
}

// ---------------------------------------------------------------------------
// Selective scan (state-in-register, shfl reduction, fused gate epilogue)
// ---------------------------------------------------------------------------
__global__ void __launch_bounds__(256)
scan_kernel(const float* __restrict__ dtg,
            const __nv_bfloat16* __restrict__ uhg,
            const __nv_bfloat16* __restrict__ ulg,
            const float* __restrict__ spg,
            const float* __restrict__ Alog,
            const float* __restrict__ Dp,
            const float* __restrict__ proj,
            __nv_bfloat16* __restrict__ yh,
            __nv_bfloat16* __restrict__ yl)
{
    const int b   = blockIdx.y;
    const int d0  = blockIdx.x * 16;
    const int t   = threadIdx.x;
    const int seq = t >> 4;
    const int n   = t & 15;
    const int d   = d0 + seq;

    __shared__ float sdt[64][16];
    __shared__ float su [64][16];
    __shared__ float sB [64][16];
    __shared__ float sC [64][16];
    __shared__ float sy [64][16];

    const float a = -__expf(Alog[d * NSTATE + n]);
    float s = 0.f;

    const int i16 = t >> 4, j16 = t & 15;
    const int i32 = t >> 5, j32 = t & 31;

    for (int l0 = 0; l0 < LSEQ; l0 += 64) {
        const int bl0 = b * LSEQ + l0;
#pragma unroll
        for (int r = 0; r < 4; r++) {
            const int ii = i16 + r * 16;
            const size_t off = (size_t)(bl0 + ii) * DDIM + d0 + j16;
            sdt[ii][j16] = dtg[off];
            su [ii][j16] = __bfloat162float(uhg[off]) + __bfloat162float(ulg[off]);
        }
#pragma unroll
        for (int r = 0; r < 8; r++) {
            const int ii = i32 + r * 8;
            const float v = spg[(size_t)(bl0 + ii) * SP_W + RRANK + j32];
            if (j32 < 16) sB[ii][j32] = v;
            else          sC[ii][j32 - 16] = v;
        }
        __syncthreads();

#pragma unroll 4
        for (int il = 0; il < 64; il++) {
            const float dtv = sdt[il][seq];
            const float dA  = __expf(a * dtv);
            const float dBu = dtv * sB[il][n] * su[il][seq];
            s = fmaf(dA, s, dBu);
            float p = s * sC[il][n];
            p += __shfl_xor_sync(0xffffffffu, p, 8);
            p += __shfl_xor_sync(0xffffffffu, p, 4);
            p += __shfl_xor_sync(0xffffffffu, p, 2);
            p += __shfl_xor_sync(0xffffffffu, p, 1);
            if (n == 0) sy[il][seq] = p;
        }
        __syncthreads();

#pragma unroll
        for (int r = 0; r < 4; r++) {
            const int ii = i16 + r * 16;
            const float yy = sy[ii][j16];
            const float uu = su[ii][j16];
            const float g  = proj[(size_t)(bl0 + ii) * P2D + DDIM + d0 + j16];
            const float yf = fmaf(uu, Dp[d0 + j16], yy) * siluf(g);
            const size_t off = (size_t)(bl0 + ii) * DDIM + d0 + j16;
            const __nv_bfloat16 h = __float2bfloat16(yf);
            yh[off] = h;
            yl[off] = __float2bfloat16(yf - __bfloat162float(h));
        }
        __syncthreads();
    }
}

// ---------------------------------------------------------------------------
// Launch sequence (graph-capturable: kernel launches only)
// ---------------------------------------------------------------------------
extern "C" void kernel_launch(void* const* d_in, const int* in_sizes, int n_in,
                              void* d_out, int out_size)
{
    const float* hs   = (const float*)d_in[0];
    const float* w_in = (const float*)d_in[1];
    const float* cw   = (const float*)d_in[2];
    const float* cb   = (const float*)d_in[3];
    const float* w_x  = (const float*)d_in[4];
    const float* w_dt = (const float*)d_in[5];
    const float* b_dt = (const float*)d_in[6];
    const float* alog = (const float*)d_in[7];
    const float* dpar = (const float*)d_in[8];
    const float* w_o  = (const float*)d_in[9];
    float* out = (float*)d_out;

    float *proj, *sp, *dtb, *xpp;
    __nv_bfloat16 *hs_h, *hs_l, *win_h, *win_l, *u_h, *u_l, *wx_h, *wx_l;
    __nv_bfloat16 *sp_h, *sp_l, *wdt_h, *wdt_l, *y_h, *y_l, *wo_h, *wo_l;
    cudaGetSymbolAddress((void**)&proj,  g_proj);
    cudaGetSymbolAddress((void**)&sp,    g_sp);
    cudaGetSymbolAddress((void**)&dtb,   g_dt);
    cudaGetSymbolAddress((void**)&xpp,   g_xpp);
    cudaGetSymbolAddress((void**)&hs_h,  g_hs_h);  cudaGetSymbolAddress((void**)&hs_l,  g_hs_l);
    cudaGetSymbolAddress((void**)&win_h, g_win_h); cudaGetSymbolAddress((void**)&win_l, g_win_l);
    cudaGetSymbolAddress((void**)&u_h,   g_u_h);   cudaGetSymbolAddress((void**)&u_l,   g_u_l);
    cudaGetSymbolAddress((void**)&wx_h,  g_wx_h);  cudaGetSymbolAddress((void**)&wx_l,  g_wx_l);
    cudaGetSymbolAddress((void**)&sp_h,  g_sp_h);  cudaGetSymbolAddress((void**)&sp_l,  g_sp_l);
    cudaGetSymbolAddress((void**)&wdt_h, g_wdt_h); cudaGetSymbolAddress((void**)&wdt_l, g_wdt_l);
    cudaGetSymbolAddress((void**)&y_h,   g_y_h);   cudaGetSymbolAddress((void**)&y_l,   g_y_l);
    cudaGetSymbolAddress((void**)&wo_h,  g_wo_h);  cudaGetSymbolAddress((void**)&wo_l,  g_wo_l);

    cudaFuncSetAttribute(tgemm_big<0>, cudaFuncAttributeMaxDynamicSharedMemorySize, BDYN_SMEM);
    cudaFuncSetAttribute(tgemm_big<1>, cudaFuncAttributeMaxDynamicSharedMemorySize, BDYN_SMEM);
    cudaFuncSetAttribute(tgemm<0, true>, cudaFuncAttributeMaxDynamicSharedMemorySize, DYN_SMEM);

    // 0) all fp32 -> bf16 hi/lo conversions in ONE launch
    cvt_all<<<(CVT_N4 + 255) / 256, 256>>>(
        hs, hs_h, hs_l, w_in, win_h, win_l, w_x, wx_h, wx_l,
        w_dt, wdt_h, wdt_l, w_o, wo_h, wo_l);

    // 1) in_proj: proj[2048, 8192] = hs @ w_in^T   (256x128 tiles)
    tgemm_big<0><<<dim3(P2D / 128, BL / 256), 256, BDYN_SMEM>>>(
        hs_h, hs_l, HDIM, win_h, win_l, HDIM, proj, P2D, HDIM, nullptr);

    // 2) conv + silu -> u (hi/lo)
    conv_silu_kernel<<<(BL * DDIM) / 256, 256>>>(proj, cw, cb, u_h, u_l);

    // 3) x_proj split-K: partials[8][2048, 160] = u @ w_x^T
    tgemm<0, true><<<dim3(2, BL / 128, XP_SPLIT), 256, DYN_SMEM>>>(
        u_h, u_l, DDIM, wx_h, wx_l, DDIM, xpp, SP_W, SP_W, XP_KLEN,
        nullptr, (size_t)BL * SP_W);

    // 3b) reduce partials -> sp (fp32) + sp hi/lo (bf16)
    xp_reduce<<<(BL * SP_W / 4 + 255) / 256, 256>>>(xpp, sp, sp_h, sp_l);

    // 4) dt_proj + bias + softplus: dt[2048, 4096]   (256x128 tiles)
    tgemm_big<1><<<dim3(DDIM / 128, BL / 256), 256, BDYN_SMEM>>>(
        sp_h, sp_l, SP_W, wdt_h, wdt_l, RRANK, dtb, DDIM, RRANK, b_dt);

    // 5) selective scan + D-skip + gate (fused) -> y (hi/lo)
    scan_kernel<<<dim3(DDIM / 16, BSZ), 256>>>(dtb, u_h, u_l, sp, alog, dpar, proj, y_h, y_l);

    // 6) out_proj: out[2048, 2048] = y @ w_o^T   (256x128 tiles)
    tgemm_big<0><<<dim3(HDIM / 128, BL / 256), 256, BDYN_SMEM>>>(
        y_h, y_l, DDIM, wo_h, wo_l, DDIM, out, HDIM, DDIM, nullptr);
}

// round 7
// speedup vs baseline: 1.1333x; 1.1333x over previous
#include <cuda_runtime.h>
#include <cuda_bf16.h>
#include <math.h>
#include <stdint.h>

// Problem constants (fixed by setup_inputs)
#define BSZ    2
#define LSEQ   1024
#define HDIM   2048
#define DDIM   4096
#define NSTATE 16
#define RRANK  128
#define KCONV  4
#define BL     (BSZ * LSEQ)          // 2048 rows
#define P2D    (2 * DDIM)            // 8192
#define SP_W   (RRANK + 2 * NSTATE)  // 160
#define XP_SPLIT 8                   // split-K factor for x_proj
#define XP_KLEN  (DDIM / XP_SPLIT)   // 512

// ---------------------------------------------------------------------------
// Scratch: static device globals (no cudaMalloc allowed)
// ---------------------------------------------------------------------------
__device__ float g_proj[(size_t)BL * P2D];     // in_proj output [BL, 8192] (u | gate)
__device__ float g_sp  [(size_t)BL * SP_W];    // x_proj output [BL, 160]
__device__ float g_dt  [(size_t)BL * DDIM];    // softplus(dt_proj) [BL, D]
__device__ float g_xpp [(size_t)XP_SPLIT * BL * SP_W];  // split-K partials

// bf16 hi/lo split buffers
__device__ __nv_bfloat16 g_hs_h[(size_t)BL * HDIM],  g_hs_l[(size_t)BL * HDIM];
__device__ __nv_bfloat16 g_win_h[(size_t)P2D * HDIM], g_win_l[(size_t)P2D * HDIM];
__device__ __nv_bfloat16 g_u_h[(size_t)BL * DDIM],   g_u_l[(size_t)BL * DDIM];
__device__ __nv_bfloat16 g_wx_h[(size_t)SP_W * DDIM], g_wx_l[(size_t)SP_W * DDIM];
__device__ __nv_bfloat16 g_sp_h[(size_t)BL * SP_W],  g_sp_l[(size_t)BL * SP_W];
__device__ __nv_bfloat16 g_wdt_h[(size_t)DDIM * RRANK], g_wdt_l[(size_t)DDIM * RRANK];
__device__ __nv_bfloat16 g_y_h[(size_t)BL * DDIM],   g_y_l[(size_t)BL * DDIM];
__device__ __nv_bfloat16 g_wo_h[(size_t)HDIM * DDIM], g_wo_l[(size_t)HDIM * DDIM];

__device__ __forceinline__ float softplusf(float x) {
    return (x > 20.f) ? x : log1pf(__expf(x));
}
__device__ __forceinline__ float siluf(float x) {
    return x / (1.f + __expf(-x));
}

// ---------------------------------------------------------------------------
// PTX helpers (sm_80+ portable: cp.async / ldmatrix / mma.sync)
// ---------------------------------------------------------------------------
__device__ __forceinline__ uint32_t smem_u32(const void* p) {
    uint32_t a;
    asm("{ .reg .u64 t; cvta.to.shared.u64 t, %1; cvt.u32.u64 %0, t; }" : "=r"(a) : "l"(p));
    return a;
}
__device__ __forceinline__ void cpa16(uint32_t dst, const void* src, int sz) {
    asm volatile("cp.async.cg.shared.global [%0], [%1], 16, %2;"
                 :: "r"(dst), "l"(src), "r"(sz) : "memory");
}
__device__ __forceinline__ void cpa16f(uint32_t dst, const void* src) {
    asm volatile("cp.async.cg.shared.global [%0], [%1], 16;"
                 :: "r"(dst), "l"(src) : "memory");
}
__device__ __forceinline__ void cpa_commit() {
    asm volatile("cp.async.commit_group;" ::: "memory");
}
template <int N>
__device__ __forceinline__ void cpa_wait() {
    asm volatile("cp.async.wait_group %0;" :: "n"(N) : "memory");
}
__device__ __forceinline__ void ldsm_x4(uint32_t* r, uint32_t addr) {
    asm volatile("ldmatrix.sync.aligned.m8n8.x4.shared.b16 {%0,%1,%2,%3}, [%4];"
                 : "=r"(r[0]), "=r"(r[1]), "=r"(r[2]), "=r"(r[3]) : "r"(addr));
}
__device__ __forceinline__ void mma_bf16(float* c, const uint32_t* a, const uint32_t* b) {
    asm volatile(
        "mma.sync.aligned.m16n8k16.row.col.f32.bf16.bf16.f32 "
        "{%0,%1,%2,%3}, {%4,%5,%6,%7}, {%8,%9}, {%0,%1,%2,%3};"
        : "+f"(c[0]), "+f"(c[1]), "+f"(c[2]), "+f"(c[3])
        : "r"(a[0]), "r"(a[1]), "r"(a[2]), "r"(a[3]), "r"(b[0]), "r"(b[1]));
}

// ---------------------------------------------------------------------------
// Merged fp32 -> bf16 hi/lo split for all 5 weight/input tensors (1 launch)
// ---------------------------------------------------------------------------
#define CVT_N0 (BL * HDIM / 4)
#define CVT_N1 (CVT_N0 + P2D * HDIM / 4)
#define CVT_N2 (CVT_N1 + SP_W * DDIM / 4)
#define CVT_N3 (CVT_N2 + DDIM * RRANK / 4)
#define CVT_N4 (CVT_N3 + HDIM * DDIM / 4)

__device__ __forceinline__ void cvt_one(const float* __restrict__ x,
                                        __nv_bfloat16* __restrict__ h,
                                        __nv_bfloat16* __restrict__ l, int i)
{
    float4 v = ((const float4*)x)[i];
    __nv_bfloat162 h0 = __floats2bfloat162_rn(v.x, v.y);
    __nv_bfloat162 h1 = __floats2bfloat162_rn(v.z, v.w);
    __nv_bfloat162 l0 = __floats2bfloat162_rn(v.x - __low2float(h0), v.y - __high2float(h0));
    __nv_bfloat162 l1 = __floats2bfloat162_rn(v.z - __low2float(h1), v.w - __high2float(h1));
    ((__nv_bfloat162*)h)[2 * i]     = h0;
    ((__nv_bfloat162*)h)[2 * i + 1] = h1;
    ((__nv_bfloat162*)l)[2 * i]     = l0;
    ((__nv_bfloat162*)l)[2 * i + 1] = l1;
}

__global__ void cvt_all(const float* s0, __nv_bfloat16* h0, __nv_bfloat16* l0,
                        const float* s1, __nv_bfloat16* h1, __nv_bfloat16* l1,
                        const float* s2, __nv_bfloat16* h2, __nv_bfloat16* l2,
                        const float* s3, __nv_bfloat16* h3, __nv_bfloat16* l3,
                        const float* s4, __nv_bfloat16* h4, __nv_bfloat16* l4)
{
    int i = blockIdx.x * blockDim.x + threadIdx.x;
    if (i < CVT_N0)      cvt_one(s0, h0, l0, i);
    else if (i < CVT_N1) cvt_one(s1, h1, l1, i - CVT_N0);
    else if (i < CVT_N2) cvt_one(s2, h2, l2, i - CVT_N1);
    else if (i < CVT_N3) cvt_one(s3, h3, l3, i - CVT_N2);
    else if (i < CVT_N4) cvt_one(s4, h4, l4, i - CVT_N3);
}

// ===========================================================================
// 4-warp split-bf16 GEMM: CTA tile 128x64, warp tile 64x32, BK=32, 3 stages.
// 72KB smem/CTA + <=168 regs => 3 CTAs/SM: smaller barriers (4 warps) and
// 3 independent pipelines per SM to cover per-chunk barrier dead time.
// C = Ah*Bh + Ah*Bl + Al*Bh (fp32 acc).  EPI==1: softplus(C + bias[n]).
// ===========================================================================
#define T4_A      8192               // 128 rows x 64B
#define T4_B      4096               // 64 rows x 64B
#define T4_STAGE  (2 * T4_A + 2 * T4_B)      // 24KB
#define T4_NSTG   3
#define T4_SMEM   (T4_NSTG * T4_STAGE)       // 72KB

template <bool GUARD>
__device__ __forceinline__ void t4_loadA(
    const __nv_bfloat16* __restrict__ src, int ld, int row0, int k0,
    uint32_t dstbase, int tid)
{
#pragma unroll
    for (int i = 0; i < 4; i++) {
        const int u   = tid + i * 128;        // 0..511
        const int row = u >> 2;               // 0..127
        const int s   = u & 3;
        const uint32_t off = (uint32_t)(row * 64 + ((s * 16) ^ ((row & 6) << 3)));
        cpa16f(dstbase + off, src + (size_t)(row0 + row) * ld + k0 + s * 8);
    }
}
template <bool GUARD>
__device__ __forceinline__ void t4_loadB(
    const __nv_bfloat16* __restrict__ src, int ld, int row0, int k0,
    uint32_t dstbase, int tid, int nrows)
{
#pragma unroll
    for (int i = 0; i < 2; i++) {
        const int u   = tid + i * 128;        // 0..255
        const int row = u >> 2;               // 0..63
        const int s   = u & 3;
        const uint32_t off = (uint32_t)(row * 64 + ((s * 16) ^ ((row & 6) << 3)));
        if (GUARD) {
            const int ok = (row0 + row) < nrows;
            const void* p = src + (size_t)(row0 + (ok ? row : 0)) * ld + k0 + s * 8;
            cpa16(dstbase + off, p, ok ? 16 : 0);
        } else {
            cpa16f(dstbase + off, src + (size_t)(row0 + row) * ld + k0 + s * 8);
        }
    }
}

template <int EPI, bool GUARD>
__global__ void __launch_bounds__(128, 3)
tgemm4(const __nv_bfloat16* __restrict__ Ah, const __nv_bfloat16* __restrict__ Al, int lda,
       const __nv_bfloat16* __restrict__ Bh, const __nv_bfloat16* __restrict__ Bl, int ldb,
       float* __restrict__ C, int ldc, int Nc, int klen,
       const float* __restrict__ bias, size_t partStride)
{
    extern __shared__ __align__(1024) char smem[];
    const uint32_t sbase = smem_u32(smem);

    const int tid  = threadIdx.x;
    const int wid  = tid >> 5;
    const int lane = tid & 31;
    const int m0   = blockIdx.y * 128;
    const int n0   = blockIdx.x * 64;
    const int kb   = blockIdx.z * klen;
    C += (size_t)blockIdx.z * partStride;
    const int wm   = wid >> 1;             // 0..1 -> 64-row slab
    const int wn   = wid & 1;              // 0..1 -> 32-col slab

    const uint32_t khiA = (uint32_t)((lane >> 4) * 16);
    const uint32_t khiB = (uint32_t)(((lane >> 3) & 1) * 16);
    uint32_t pA[4], xA[4], pB[2], xB[2];
#pragma unroll
    for (int i = 0; i < 4; i++) {
        const int r = wm * 64 + i * 16 + (lane & 15);
        pA[i] = (uint32_t)(r * 64);
        xA[i] = (uint32_t)((r & 6) << 3);
    }
#pragma unroll
    for (int j2 = 0; j2 < 2; j2++) {
        const int r = wn * 32 + j2 * 16 + ((lane >> 4) << 3) + (lane & 7);
        pB[j2] = (uint32_t)(r * 64);
        xB[j2] = (uint32_t)((r & 6) << 3);
    }

    float acc[4][4][4];
#pragma unroll
    for (int i = 0; i < 4; i++)
#pragma unroll
        for (int j = 0; j < 4; j++)
#pragma unroll
            for (int r = 0; r < 4; r++) acc[i][j][r] = 0.f;

    const int nch = klen >> 5;

#pragma unroll
    for (int s = 0; s < T4_NSTG - 1; s++) {
        if (s < nch) {
            uint32_t st = sbase + s * T4_STAGE;
            const int k0 = kb + (s << 5);
            t4_loadA<false>(Ah, lda, m0, k0, st,            tid);
            t4_loadA<false>(Al, lda, m0, k0, st + T4_A,     tid);
            t4_loadB<GUARD>(Bh, ldb, n0, k0, st + 2 * T4_A,        tid, Nc);
            t4_loadB<GUARD>(Bl, ldb, n0, k0, st + 2 * T4_A + T4_B, tid, Nc);
        }
        cpa_commit();
    }

    for (int c = 0; c < nch; c++) {
        cpa_wait<T4_NSTG - 2>();
        __syncthreads();

        const int cp = c + T4_NSTG - 1;
        if (cp < nch) {
            uint32_t st = sbase + (cp % T4_NSTG) * T4_STAGE;
            const int k0 = kb + (cp << 5);
            t4_loadA<false>(Ah, lda, m0, k0, st,            tid);
            t4_loadA<false>(Al, lda, m0, k0, st + T4_A,     tid);
            t4_loadB<GUARD>(Bh, ldb, n0, k0, st + 2 * T4_A,        tid, Nc);
            t4_loadB<GUARD>(Bl, ldb, n0, k0, st + 2 * T4_A + T4_B, tid, Nc);
        }
        cpa_commit();

        const uint32_t aH = sbase + (c % T4_NSTG) * T4_STAGE;
        const uint32_t aL = aH + T4_A;
        const uint32_t bH = aH + 2 * T4_A;
        const uint32_t bL = bH + T4_B;

#pragma unroll
        for (int ks = 0; ks < 2; ks++) {
            const uint32_t kA = (uint32_t)(ks * 32) + khiA;
            const uint32_t kB = (uint32_t)(ks * 32) + khiB;
            uint32_t ah[4][4], al[4][4];
#pragma unroll
            for (int i = 0; i < 4; i++) {
                ldsm_x4(ah[i], aH + pA[i] + (kA ^ xA[i]));
                ldsm_x4(al[i], aL + pA[i] + (kA ^ xA[i]));
            }
            uint32_t bh[2][4], bl[2][4];
#pragma unroll
            for (int j2 = 0; j2 < 2; j2++) {
                ldsm_x4(bh[j2], bH + pB[j2] + (kB ^ xB[j2]));
                ldsm_x4(bl[j2], bL + pB[j2] + (kB ^ xB[j2]));
            }
            // term-major: acc reuse distance = 16 independent MMAs
#pragma unroll
            for (int j = 0; j < 4; j++)
#pragma unroll
                for (int i = 0; i < 4; i++)
                    mma_bf16(acc[i][j], ah[i], &bh[j >> 1][(j & 1) * 2]);
#pragma unroll
            for (int j = 0; j < 4; j++)
#pragma unroll
                for (int i = 0; i < 4; i++)
                    mma_bf16(acc[i][j], ah[i], &bl[j >> 1][(j & 1) * 2]);
#pragma unroll
            for (int j = 0; j < 4; j++)
#pragma unroll
                for (int i = 0; i < 4; i++)
                    mma_bf16(acc[i][j], al[i], &bh[j >> 1][(j & 1) * 2]);
        }
    }

    const int qr = lane >> 2;
    const int qc = (lane & 3) * 2;
#pragma unroll
    for (int i = 0; i < 4; i++) {
        const int r0 = m0 + wm * 64 + i * 16 + qr;
#pragma unroll
        for (int j = 0; j < 4; j++) {
            const int nn = n0 + wn * 32 + j * 8 + qc;
            if (!GUARD || nn < Nc) {
                float2 v0 = make_float2(acc[i][j][0], acc[i][j][1]);
                float2 v1 = make_float2(acc[i][j][2], acc[i][j][3]);
                if (EPI == 1) {
                    const float b0 = bias[nn], b1 = bias[nn + 1];
                    v0.x = softplusf(v0.x + b0); v0.y = softplusf(v0.y + b1);
                    v1.x = softplusf(v1.x + b0); v1.y = softplusf(v1.y + b1);
                }
                *(float2*)(C + (size_t)r0 * ldc + nn)       = v0;
                *(float2*)(C + (size_t)(r0 + 8) * ldc + nn) = v1;
            }
        }
    }
}

// ---------------------------------------------------------------------------
// 8-warp split-bf16 GEMM (128x128 tile, 2 CTAs/SM) — used for out_proj
// (grid 256 fits a single wave at 2 CTAs/SM; proven R5 config)
// ---------------------------------------------------------------------------
#define TILE_BYTES  8192
#define STAGE_BYTES (4 * TILE_BYTES)
#define NSTAGE      3
#define DYN_SMEM    (NSTAGE * STAGE_BYTES)

__device__ __forceinline__ void load_tile_async8(
    const __nv_bfloat16* __restrict__ src, int ld, int row0, int k0,
    uint32_t dstbase, int tid)
{
#pragma unroll
    for (int i = 0; i < 2; i++) {
        const int u   = tid + i * 256;
        const int row = u >> 2;
        const int s   = u & 3;
        const uint32_t off = (uint32_t)(row * 64 + ((s * 16) ^ ((row & 6) << 3)));
        cpa16f(dstbase + off, src + (size_t)(row0 + row) * ld + k0 + s * 8);
    }
}

__global__ void __launch_bounds__(256, 2)
tgemm8(const __nv_bfloat16* __restrict__ Ah, const __nv_bfloat16* __restrict__ Al, int lda,
       const __nv_bfloat16* __restrict__ Bh, const __nv_bfloat16* __restrict__ Bl, int ldb,
       float* __restrict__ C, int ldc, int klen)
{
    extern __shared__ __align__(1024) char smem[];
    const uint32_t sbase = smem_u32(smem);

    const int tid  = threadIdx.x;
    const int wid  = tid >> 5;
    const int lane = tid & 31;
    const int m0   = blockIdx.y * 128;
    const int n0   = blockIdx.x * 128;
    const int wm   = wid >> 2;
    const int wn   = wid & 3;

    const uint32_t khiA = (uint32_t)((lane >> 4) * 16);
    const uint32_t khiB = (uint32_t)(((lane >> 3) & 1) * 16);
    uint32_t pA[4], xA[4], pB[2], xB[2];
#pragma unroll
    for (int i = 0; i < 4; i++) {
        const int r = wm * 64 + i * 16 + (lane & 15);
        pA[i] = (uint32_t)(r * 64);
        xA[i] = (uint32_t)((r & 6) << 3);
    }
#pragma unroll
    for (int j2 = 0; j2 < 2; j2++) {
        const int r = wn * 32 + j2 * 16 + ((lane >> 4) << 3) + (lane & 7);
        pB[j2] = (uint32_t)(r * 64);
        xB[j2] = (uint32_t)((r & 6) << 3);
    }

    float acc[4][4][4];
#pragma unroll
    for (int i = 0; i < 4; i++)
#pragma unroll
        for (int j = 0; j < 4; j++)
#pragma unroll
            for (int r = 0; r < 4; r++) acc[i][j][r] = 0.f;

    const int nch = klen >> 5;

#pragma unroll
    for (int s = 0; s < NSTAGE - 1; s++) {
        if (s < nch) {
            uint32_t st = sbase + s * STAGE_BYTES;
            const int k0 = s << 5;
            load_tile_async8(Ah, lda, m0, k0, st,                  tid);
            load_tile_async8(Al, lda, m0, k0, st + TILE_BYTES,     tid);
            load_tile_async8(Bh, ldb, n0, k0, st + 2 * TILE_BYTES, tid);
            load_tile_async8(Bl, ldb, n0, k0, st + 3 * TILE_BYTES, tid);
        }
        cpa_commit();
    }

    for (int c = 0; c < nch; c++) {
        cpa_wait<NSTAGE - 2>();
        __syncthreads();

        const int cp = c + NSTAGE - 1;
        if (cp < nch) {
            uint32_t st = sbase + (cp % NSTAGE) * STAGE_BYTES;
            const int k0 = cp << 5;
            load_tile_async8(Ah, lda, m0, k0, st,                  tid);
            load_tile_async8(Al, lda, m0, k0, st + TILE_BYTES,     tid);
            load_tile_async8(Bh, ldb, n0, k0, st + 2 * TILE_BYTES, tid);
            load_tile_async8(Bl, ldb, n0, k0, st + 3 * TILE_BYTES, tid);
        }
        cpa_commit();

        const uint32_t aH = sbase + (c % NSTAGE) * STAGE_BYTES;
        const uint32_t aL = aH + TILE_BYTES;
        const uint32_t bH = aH + 2 * TILE_BYTES;
        const uint32_t bL = aH + 3 * TILE_BYTES;

#pragma unroll
        for (int ks = 0; ks < 2; ks++) {
            const uint32_t kA = (uint32_t)(ks * 32) + khiA;
            const uint32_t kB = (uint32_t)(ks * 32) + khiB;
            uint32_t ah[4][4], al[4][4];
#pragma unroll
            for (int i = 0; i < 4; i++) {
                ldsm_x4(ah[i], aH + pA[i] + (kA ^ xA[i]));
                ldsm_x4(al[i], aL + pA[i] + (kA ^ xA[i]));
            }
            uint32_t bh[2][4], bl[2][4];
#pragma unroll
            for (int j2 = 0; j2 < 2; j2++) {
                ldsm_x4(bh[j2], bH + pB[j2] + (kB ^ xB[j2]));
                ldsm_x4(bl[j2], bL + pB[j2] + (kB ^ xB[j2]));
            }
#pragma unroll
            for (int j = 0; j < 4; j++)
#pragma unroll
                for (int i = 0; i < 4; i++)
                    mma_bf16(acc[i][j], ah[i], &bh[j >> 1][(j & 1) * 2]);
#pragma unroll
            for (int j = 0; j < 4; j++)
#pragma unroll
                for (int i = 0; i < 4; i++)
                    mma_bf16(acc[i][j], ah[i], &bl[j >> 1][(j & 1) * 2]);
#pragma unroll
            for (int j = 0; j < 4; j++)
#pragma unroll
                for (int i = 0; i < 4; i++)
                    mma_bf16(acc[i][j], al[i], &bh[j >> 1][(j & 1) * 2]);
        }
    }

    const int qr = lane >> 2;
    const int qc = (lane & 3) * 2;
#pragma unroll
    for (int i = 0; i < 4; i++) {
        const int r0 = m0 + wm * 64 + i * 16 + qr;
#pragma unroll
        for (int j = 0; j < 4; j++) {
            const int nn = n0 + wn * 32 + j * 8 + qc;
            *(float2*)(C + (size_t)r0 * ldc + nn)       = make_float2(acc[i][j][0], acc[i][j][1]);
            *(float2*)(C + (size_t)(r0 + 8) * ldc + nn) = make_float2(acc[i][j][2], acc[i][j][3]);
        }
    }
}

// ---------------------------------------------------------------------------
// split-K reduce for x_proj: sp = sum(partials); also emit bf16 hi/lo
// ---------------------------------------------------------------------------
__global__ void xp_reduce(const float* __restrict__ part,
                          float* __restrict__ sp,
                          __nv_bfloat16* __restrict__ sph,
                          __nv_bfloat16* __restrict__ spl)
{
    const int n4 = BL * SP_W / 4;
    int i = blockIdx.x * blockDim.x + threadIdx.x;
    if (i >= n4) return;
    float4 a = ((const float4*)part)[i];
#pragma unroll
    for (int p = 1; p < XP_SPLIT; p++) {
        float4 b = ((const float4*)part)[i + (size_t)p * n4];
        a.x += b.x; a.y += b.y; a.z += b.z; a.w += b.w;
    }
    ((float4*)sp)[i] = a;
    __nv_bfloat162 h0 = __floats2bfloat162_rn(a.x, a.y);
    __nv_bfloat162 h1 = __floats2bfloat162_rn(a.z, a.w);
    __nv_bfloat162 l0 = __floats2bfloat162_rn(a.x - __low2float(h0), a.y - __high2float(h0));
    __nv_bfloat162 l1 = __floats2bfloat162_rn(a.z - __low2float(h1), a.w - __high2float(h1));
    ((__nv_bfloat162*)sph)[2 * i]     = h0;
    ((__nv_bfloat162*)sph)[2 * i + 1] = h1;
    ((__nv_bfloat162*)spl)[2 * i]     = l0;
    ((__nv_bfloat162*)spl)[2 * i + 1] = l1;
}

// ---------------------------------------------------------------------------
// Depthwise causal conv1d (K=4) + bias + silu -> bf16 hi/lo
// Tiled: each thread computes 4 consecutive l for one d (7 loads / 4 outputs)
// ---------------------------------------------------------------------------
__global__ void conv_silu_kernel(const float* __restrict__ proj,
                                 const float* __restrict__ cw,
                                 const float* __restrict__ cb,
                                 __nv_bfloat16* __restrict__ uh,
                                 __nv_bfloat16* __restrict__ ul)
{
    const int t = blockIdx.x * blockDim.x + threadIdx.x;
    if (t >= (BL / 4) * DDIM) return;
    const int d   = t & (DDIM - 1);
    const int q   = t >> 12;          // 0 .. BL/4-1
    const int bl0 = q * 4;
    const int l0  = bl0 & (LSEQ - 1); // multiple of 4; only l0==0 underflows

    const float4 w = *(const float4*)(cw + d * 4);
    const float  b = cb[d];
    const float* base = proj + (size_t)bl0 * P2D + d;
    const bool   lz = (l0 == 0);

    float x[7];
#pragma unroll
    for (int i = 0; i < 7; i++)
        x[i] = (!lz || i >= 3) ? base[(i - 3) * P2D] : 0.f;

#pragma unroll
    for (int k = 0; k < 4; k++) {
        float acc = b;
        acc = fmaf(w.x, x[k],     acc);
        acc = fmaf(w.y, x[k + 1], acc);
        acc = fmaf(w.z, x[k + 2], acc);
        acc = fmaf(w.w, x[k + 3], acc);
        const float v = siluf(acc);
        const __nv_bfloat16 h = __float2bfloat16(v);
        const size_t off = (size_t)(bl0 + k) * DDIM + d;
        uh[off] = h;
        ul[off] = __float2bfloat16(v - __bfloat162float(h));
    }
}

// ---------------------------------------------------------------------------
// Selective scan (state-in-register, shfl reduction, fused gate epilogue)
// ---------------------------------------------------------------------------
__global__ void __launch_bounds__(256)
scan_kernel(const float* __restrict__ dtg,
            const __nv_bfloat16* __restrict__ uhg,
            const __nv_bfloat16* __restrict__ ulg,
            const float* __restrict__ spg,
            const float* __restrict__ Alog,
            const float* __restrict__ Dp,
            const float* __restrict__ proj,
            __nv_bfloat16* __restrict__ yh,
            __nv_bfloat16* __restrict__ yl)
{
    const int b   = blockIdx.y;
    const int d0  = blockIdx.x * 16;
    const int t   = threadIdx.x;
    const int seq = t >> 4;
    const int n   = t & 15;
    const int d   = d0 + seq;

    __shared__ float sdt[64][16];
    __shared__ float su [64][16];
    __shared__ float sB [64][16];
    __shared__ float sC [64][16];
    __shared__ float sy [64][16];

    const float a = -__expf(Alog[d * NSTATE + n]);
    float s = 0.f;

    const int i16 = t >> 4, j16 = t & 15;
    const int i32 = t >> 5, j32 = t & 31;

    for (int l0 = 0; l0 < LSEQ; l0 += 64) {
        const int bl0 = b * LSEQ + l0;
#pragma unroll
        for (int r = 0; r < 4; r++) {
            const int ii = i16 + r * 16;
            const size_t off = (size_t)(bl0 + ii) * DDIM + d0 + j16;
            sdt[ii][j16] = dtg[off];
            su [ii][j16] = __bfloat162float(uhg[off]) + __bfloat162float(ulg[off]);
        }
#pragma unroll
        for (int r = 0; r < 8; r++) {
            const int ii = i32 + r * 8;
            const float v = spg[(size_t)(bl0 + ii) * SP_W + RRANK + j32];
            if (j32 < 16) sB[ii][j32] = v;
            else          sC[ii][j32 - 16] = v;
        }
        __syncthreads();

#pragma unroll 4
        for (int il = 0; il < 64; il++) {
            const float dtv = sdt[il][seq];
            const float dA  = __expf(a * dtv);
            const float dBu = dtv * sB[il][n] * su[il][seq];
            s = fmaf(dA, s, dBu);
            float p = s * sC[il][n];
            p += __shfl_xor_sync(0xffffffffu, p, 8);
            p += __shfl_xor_sync(0xffffffffu, p, 4);
            p += __shfl_xor_sync(0xffffffffu, p, 2);
            p += __shfl_xor_sync(0xffffffffu, p, 1);
            if (n == 0) sy[il][seq] = p;
        }
        __syncthreads();

#pragma unroll
        for (int r = 0; r < 4; r++) {
            const int ii = i16 + r * 16;
            const float yy = sy[ii][j16];
            const float uu = su[ii][j16];
            const float g  = proj[(size_t)(bl0 + ii) * P2D + DDIM + d0 + j16];
            const float yf = fmaf(uu, Dp[d0 + j16], yy) * siluf(g);
            const size_t off = (size_t)(bl0 + ii) * DDIM + d0 + j16;
            const __nv_bfloat16 h = __float2bfloat16(yf);
            yh[off] = h;
            yl[off] = __float2bfloat16(yf - __bfloat162float(h));
        }
        __syncthreads();
    }
}

// ---------------------------------------------------------------------------
// Launch sequence (graph-capturable: kernel launches only)
// ---------------------------------------------------------------------------
extern "C" void kernel_launch(void* const* d_in, const int* in_sizes, int n_in,
                              void* d_out, int out_size)
{
    const float* hs   = (const float*)d_in[0];
    const float* w_in = (const float*)d_in[1];
    const float* cw   = (const float*)d_in[2];
    const float* cb   = (const float*)d_in[3];
    const float* w_x  = (const float*)d_in[4];
    const float* w_dt = (const float*)d_in[5];
    const float* b_dt = (const float*)d_in[6];
    const float* alog = (const float*)d_in[7];
    const float* dpar = (const float*)d_in[8];
    const float* w_o  = (const float*)d_in[9];
    float* out = (float*)d_out;

    float *proj, *sp, *dtb, *xpp;
    __nv_bfloat16 *hs_h, *hs_l, *win_h, *win_l, *u_h, *u_l, *wx_h, *wx_l;
    __nv_bfloat16 *sp_h, *sp_l, *wdt_h, *wdt_l, *y_h, *y_l, *wo_h, *wo_l;
    cudaGetSymbolAddress((void**)&proj,  g_proj);
    cudaGetSymbolAddress((void**)&sp,    g_sp);
    cudaGetSymbolAddress((void**)&dtb,   g_dt);
    cudaGetSymbolAddress((void**)&xpp,   g_xpp);
    cudaGetSymbolAddress((void**)&hs_h,  g_hs_h);  cudaGetSymbolAddress((void**)&hs_l,  g_hs_l);
    cudaGetSymbolAddress((void**)&win_h, g_win_h); cudaGetSymbolAddress((void**)&win_l, g_win_l);
    cudaGetSymbolAddress((void**)&u_h,   g_u_h);   cudaGetSymbolAddress((void**)&u_l,   g_u_l);
    cudaGetSymbolAddress((void**)&wx_h,  g_wx_h);  cudaGetSymbolAddress((void**)&wx_l,  g_wx_l);
    cudaGetSymbolAddress((void**)&sp_h,  g_sp_h);  cudaGetSymbolAddress((void**)&sp_l,  g_sp_l);
    cudaGetSymbolAddress((void**)&wdt_h, g_wdt_h); cudaGetSymbolAddress((void**)&wdt_l, g_wdt_l);
    cudaGetSymbolAddress((void**)&y_h,   g_y_h);   cudaGetSymbolAddress((void**)&y_l,   g_y_l);
    cudaGetSymbolAddress((void**)&wo_h,  g_wo_h);  cudaGetSymbolAddress((void**)&wo_l,  g_wo_l);

    cudaFuncSetAttribute(tgemm4<0, false>, cudaFuncAttributeMaxDynamicSharedMemorySize, T4_SMEM);
    cudaFuncSetAttribute(tgemm4<0, true>,  cudaFuncAttributeMaxDynamicSharedMemorySize, T4_SMEM);
    cudaFuncSetAttribute(tgemm4<1, false>, cudaFuncAttributeMaxDynamicSharedMemorySize, T4_SMEM);
    cudaFuncSetAttribute(tgemm8,           cudaFuncAttributeMaxDynamicSharedMemorySize, DYN_SMEM);

    // 0) all fp32 -> bf16 hi/lo conversions in ONE launch
    cvt_all<<<(CVT_N4 + 255) / 256, 256>>>(
        hs, hs_h, hs_l, w_in, win_h, win_l, w_x, wx_h, wx_l,
        w_dt, wdt_h, wdt_l, w_o, wo_h, wo_l);

    // 1) in_proj: proj[2048, 8192] = hs @ w_in^T   (128x64 tiles, 3 CTA/SM)
    tgemm4<0, false><<<dim3(P2D / 64, BL / 128, 1), 128, T4_SMEM>>>(
        hs_h, hs_l, HDIM, win_h, win_l, HDIM, proj, P2D, P2D, HDIM, nullptr, 0);

    // 2) conv + silu -> u (hi/lo)  (tiled: 4 l per thread)
    conv_silu_kernel<<<(BL / 4 * DDIM) / 256, 256>>>(proj, cw, cb, u_h, u_l);

    // 3) x_proj split-K: partials[8][2048, 160] = u @ w_x^T
    tgemm4<0, true><<<dim3(3, BL / 128, XP_SPLIT), 128, T4_SMEM>>>(
        u_h, u_l, DDIM, wx_h, wx_l, DDIM, xpp, SP_W, SP_W, XP_KLEN,
        nullptr, (size_t)BL * SP_W);

    // 3b) reduce partials -> sp (fp32) + sp hi/lo (bf16)
    xp_reduce<<<(BL * SP_W / 4 + 255) / 256, 256>>>(xpp, sp, sp_h, sp_l);

    // 4) dt_proj + bias + softplus: dt[2048, 4096]
    tgemm4<1, false><<<dim3(DDIM / 64, BL / 128, 1), 128, T4_SMEM>>>(
        sp_h, sp_l, SP_W, wdt_h, wdt_l, RRANK, dtb, DDIM, DDIM, RRANK, b_dt, 0);

    // 5) selective scan + D-skip + gate (fused) -> y (hi/lo)
    scan_kernel<<<dim3(DDIM / 16, BSZ), 256>>>(dtb, u_h, u_l, sp, alog, dpar, proj, y_h, y_l);

    // 6) out_proj: out[2048, 2048] = y @ w_o^T   (128x128 tiles, 2 CTA/SM)
    tgemm8<<<dim3(HDIM / 128, BL / 128, 1), 256, DYN_SMEM>>>(
        y_h, y_l, DDIM, wo_h, wo_l, DDIM, out, HDIM, DDIM);
}